// round 8
// baseline (speedup 1.0000x reference)
#include <cuda_runtime.h>
#include <cuda_bf16.h>
#include <cuda_fp16.h>
#include <cstdint>

#define NB 2
#define NS 2048
#define NDM 512
#define NH 8
#define NDH 64
#define LOG2E 1.4426950408889634f

// ---------------------------------------------------------------------------
// Scratch (__device__ globals; no allocation allowed)
// ---------------------------------------------------------------------------
__device__ __half g_A16[3*4096*512];        // inputs (q,k,v), single fp16
__device__ __half g_Wt16[4*512*512];        // transposed weights [n][k], fp16
__device__ __half g_Qh16[NB*NH*NS*NDH];     // head-layout projections (fp16)
__device__ __half g_Kh16[NB*NH*NS*NDH];
__device__ __half g_Vh16[NB*NH*NS*NDH];
__device__ __half g_attnh16[4096*512];      // attention output hi (merged heads)
__device__ __half g_attnl16[4096*512];      // lo

// ---------------------------------------------------------------------------
// PTX helpers (baseline sm_80+ instructions only)
// ---------------------------------------------------------------------------
__device__ __forceinline__ uint32_t smem_u32(const void* p) {
    uint32_t a;
    asm("{ .reg .u64 t; cvta.to.shared.u64 t, %1; cvt.u32.u64 %0, t; }" : "=r"(a) : "l"(p));
    return a;
}
__device__ __forceinline__ void mma16816h(float* c, const uint32_t* a, const uint32_t* b) {
    asm volatile(
        "mma.sync.aligned.m16n8k16.row.col.f32.f16.f16.f32 "
        "{%0,%1,%2,%3}, {%4,%5,%6,%7}, {%8,%9}, {%0,%1,%2,%3};"
        : "+f"(c[0]), "+f"(c[1]), "+f"(c[2]), "+f"(c[3])
        : "r"(a[0]), "r"(a[1]), "r"(a[2]), "r"(a[3]), "r"(b[0]), "r"(b[1]));
}
__device__ __forceinline__ void ldsm_x4(uint32_t* r, uint32_t addr) {
    asm volatile("ldmatrix.sync.aligned.m8n8.x4.shared.b16 {%0,%1,%2,%3}, [%4];"
        : "=r"(r[0]), "=r"(r[1]), "=r"(r[2]), "=r"(r[3]) : "r"(addr));
}
__device__ __forceinline__ void ldsm_x4_t(uint32_t* r, uint32_t addr) {
    asm volatile("ldmatrix.sync.aligned.m8n8.x4.trans.shared.b16 {%0,%1,%2,%3}, [%4];"
        : "=r"(r[0]), "=r"(r[1]), "=r"(r[2]), "=r"(r[3]) : "r"(addr));
}
__device__ __forceinline__ void cpa16(uint32_t dst, const void* src) {
    asm volatile("cp.async.cg.shared.global [%0], [%1], 16;" :: "r"(dst), "l"(src));
}
#define CP_COMMIT() asm volatile("cp.async.commit_group;")
__device__ __forceinline__ uint32_t sw128(uint32_t off) {
    return off ^ ((off >> 3) & 0x70);
}
__device__ __forceinline__ float ex2f(float x) {
    float y; asm("ex2.approx.f32 %0, %1;" : "=f"(y) : "f"(x)); return y;
}
__device__ __forceinline__ uint32_t pack_h2(float a, float b) {
    __half2 t = __floats2half2_rn(a, b);
    return *reinterpret_cast<uint32_t*>(&t);
}
__device__ __forceinline__ void split2h(float v0, float v1, uint32_t& hi, uint32_t& lo) {
    __half h0 = __float2half_rn(v0);
    __half h1 = __float2half_rn(v1);
    __half l0 = __float2half_rn(v0 - __half2float(h0));
    __half l1 = __float2half_rn(v1 - __half2float(h1));
    __half2 hp = __halves2half2(h0, h1);
    __half2 lp = __halves2half2(l0, l1);
    hi = *reinterpret_cast<uint32_t*>(&hp);
    lo = *reinterpret_cast<uint32_t*>(&lp);
}

// ---------------------------------------------------------------------------
// Conversion kernels
// ---------------------------------------------------------------------------
__global__ void __launch_bounds__(256) conv_in_kernel(
    const float* __restrict__ q, const float* __restrict__ k, const float* __restrict__ v)
{
    const int z = blockIdx.z;
    const float* x = (z == 0) ? q : (z == 1) ? k : v;
    const size_t idx = ((size_t)blockIdx.x * 256 + threadIdx.x) * 4;
    float4 a = *reinterpret_cast<const float4*>(x + idx);
    const size_t o = (size_t)z * 4096 * 512 + idx;
    *reinterpret_cast<uint2*>(&g_A16[o]) =
        make_uint2(pack_h2(a.x, a.y), pack_h2(a.z, a.w));
}

__global__ void conv_w_kernel(
    const float* __restrict__ wq, const float* __restrict__ wk,
    const float* __restrict__ wv, const float* __restrict__ wo)
{
    const int z = blockIdx.z;
    const float* w = (z == 0) ? wq : (z == 1) ? wk : (z == 2) ? wv : wo;
    __shared__ float t[32][33];
    const int n0 = blockIdx.x * 32, k0 = blockIdx.y * 32;
    const int tx = threadIdx.x, ty = threadIdx.y;
    #pragma unroll
    for (int i = 0; i < 4; ++i)
        t[ty + 8*i][tx] = w[(size_t)(k0 + ty + 8*i) * 512 + n0 + tx];
    __syncthreads();
    #pragma unroll
    for (int i = 0; i < 4; ++i) {
        const int n = n0 + ty + 8*i, kk = k0 + tx;
        g_Wt16[(size_t)z * 262144 + (size_t)n * 512 + kk] = __float2half_rn(t[tx][ty + 8*i]);
    }
}

// ---------------------------------------------------------------------------
// fp16 HMMA GEMM, 64x128 tile, K-chunk 64, 8 warps (4m x 2n), 2-stage cp.async.
// MODE 0: qkv — A single fp16 (1 pass); writes fp16 head layout (Q scaled 1/8)
// MODE 1: out — A split hi+lo (2 passes, exact A); writes fp32 flat + bias
// ---------------------------------------------------------------------------
template<int MODE>
__global__ void __launch_bounds__(256, 2) gemm_mma_kernel(
    const float* __restrict__ b0, const float* __restrict__ b1,
    const float* __restrict__ b2, float* __restrict__ outp)
{
    constexpr uint32_t STAGE = (MODE == 0) ? 24576u : 32768u;  // A 8K (+Al 8K) + W 16K
    constexpr uint32_t WOFF  = (MODE == 0) ? 8192u  : 16384u;

    extern __shared__ char smem[];
    const uint32_t sb = smem_u32(smem);
    const int tid  = threadIdx.x;
    const int lane = tid & 31;
    const int warp = tid >> 5;
    const int wm   = warp & 3;
    const int wn   = warp >> 2;
    const int z    = (MODE == 0) ? blockIdx.z : 3;
    const int n0   = blockIdx.x * 128;
    const int m0   = blockIdx.y * 64;

    const char* Ah = (MODE == 0) ? (const char*)(g_A16 + (size_t)z*4096*512)
                                 : (const char*)g_attnh16;
    const char* Al = (const char*)g_attnl16;   // MODE 1 only
    const char* Wp = (const char*)(g_Wt16 + (size_t)z*262144);
    const float* bias = (MODE == 0) ? ((z == 0) ? b0 : (z == 1) ? b1 : b2) : b0;

    auto load_chunk = [&](int c, int st) {
        const uint32_t base = sb + (uint32_t)st * STAGE;
        #pragma unroll
        for (int i = 0; i < 2; ++i) {                 // A: 64 rows x 8 segs
            const int e = tid + 256*i;
            const int row = e >> 3, seg = e & 7;
            const uint32_t sw = sw128((uint32_t)row*128u + seg*16u);
            const size_t aoff = (size_t)(m0 + row)*1024 + (size_t)c*128 + seg*16;
            cpa16(base + sw, Ah + aoff);
            if (MODE == 1) cpa16(base + 8192 + sw, Al + aoff);
        }
        #pragma unroll
        for (int i = 0; i < 4; ++i) {                 // W: 128 rows x 8 segs
            const int e = tid + 256*i;
            const int row = e >> 3, seg = e & 7;
            const uint32_t sw = sw128((uint32_t)row*128u + seg*16u);
            const size_t woff = (size_t)(n0 + row)*1024 + (size_t)c*128 + seg*16;
            cpa16(base + WOFF + sw, Wp + woff);
        }
        CP_COMMIT();
    };

    float acc[8][4];
    #pragma unroll
    for (int bq = 0; bq < 8; ++bq)
        #pragma unroll
        for (int cI = 0; cI < 4; ++cI) acc[bq][cI] = 0.f;

    const int g  = lane >> 3, lr = lane & 7;
    const int arow = wm*16 + lr + ((g & 1) ? 8 : 0);
    const int acol = (g >= 2) ? 16 : 0;
    const int brow = lr + ((g >= 2) ? 8 : 0);
    const int bcol = (g & 1) ? 16 : 0;

    load_chunk(0, 0);
    for (int c = 0; c < 8; ++c) {
        if (c < 7) {
            load_chunk(c + 1, (c + 1) & 1);
            asm volatile("cp.async.wait_group 1;" ::: "memory");
        } else {
            asm volatile("cp.async.wait_group 0;" ::: "memory");
        }
        __syncthreads();
        const uint32_t stb = sb + (uint32_t)(c & 1) * STAGE;
        #pragma unroll
        for (int ks = 0; ks < 4; ++ks) {
            uint32_t ah0[4], al0[4];
            const uint32_t sw0 = sw128((uint32_t)arow*128u + 32*ks + acol);
            ldsm_x4(ah0, stb + sw0);
            if (MODE == 1) ldsm_x4(al0, stb + 8192 + sw0);
            #pragma unroll
            for (int np = 0; np < 4; ++np) {
                const uint32_t sw = sw128((uint32_t)(wn*64 + np*16 + brow)*128u + 32*ks + bcol);
                uint32_t w4[4];
                ldsm_x4(w4, stb + WOFF + sw);
                mma16816h(acc[2*np],   ah0, w4); mma16816h(acc[2*np+1], ah0, w4+2);
                if (MODE == 1) {
                    mma16816h(acc[2*np], al0, w4); mma16816h(acc[2*np+1], al0, w4+2);
                }
            }
        }
        __syncthreads();
    }

    // epilogue
    const int r  = lane >> 2;
    const int tq = lane & 3;
    const float sc = (MODE == 0 && z == 0) ? 0.125f : 1.f;
    __half* outh = (z == 0) ? g_Qh16 : (z == 1) ? g_Kh16 : g_Vh16;
    #pragma unroll
    for (int np = 0; np < 4; ++np) {
        #pragma unroll
        for (int sub = 0; sub < 2; ++sub) {
            const float* c4 = acc[2*np + sub];
            const int row0 = m0 + wm*16 + r;
            const int col  = n0 + wn*64 + np*16 + sub*8 + 2*tq;
            const float bv0 = bias[col], bv1 = bias[col + 1];
            if (MODE == 1) {
                *reinterpret_cast<float2*>(outp + (size_t)row0*512 + col) =
                    make_float2(c4[0] + bv0, c4[1] + bv1);
                *reinterpret_cast<float2*>(outp + (size_t)(row0+8)*512 + col) =
                    make_float2(c4[2] + bv0, c4[3] + bv1);
            } else {
                #pragma unroll
                for (int rr = 0; rr < 2; ++rr) {
                    const int row = row0 + rr*8;
                    const int bb = row >> 11, s = row & 2047;
                    const int hh = col >> 6,  d = col & 63;
                    const size_t o = (((size_t)bb*NH + hh)*NS + s)*NDH + d;
                    *reinterpret_cast<uint32_t*>(&outh[o]) =
                        pack_h2((c4[2*rr] + bv0)*sc, (c4[2*rr+1] + bv1)*sc);
                }
            }
        }
    }
}

// ---------------------------------------------------------------------------
// Flash attention (HMMA fp16), key-split warps.
// CTA = 64 queries, 8 warps: warp = (q-group 0-3, key-half 0-1).
// Each warp: S = Qh@Kh over its 32 keys (4 ILP chains), fp32-mask softmax,
// O += P@V partial. Key-halves combined once at the end via smem.
// 4-stage cp.async KV pipeline. Writes split-fp16 merged-head output.
// ---------------------------------------------------------------------------
#define A_Q      0
#define A_KV     8192
#define KV_STAGE 16384          // Kh 8K | Vh 8K
#define ATT_SMEM (A_KV + 4*KV_STAGE)   // 73728

__global__ void __launch_bounds__(256, 2) attn_mma_kernel(const float* __restrict__ mask)
{
    extern __shared__ char smem[];
    const uint32_t sb = smem_u32(smem);
    const int tid  = threadIdx.x;
    const int lane = tid & 31;
    const int warp = tid >> 5;
    const int qg   = warp & 3;      // q-group (16 rows)
    const int kh   = warp >> 2;     // key-half (32 of 64 keys)
    const int bh   = blockIdx.y;
    const int b    = bh >> 3;
    const int h    = bh & 7;
    const int q0   = blockIdx.x * 64;

    const int g  = lane >> 3, lr = lane & 7;
    const int r  = lane >> 2, tq = lane & 3;

    const char* Khp = (const char*)(g_Kh16 + (size_t)bh*NS*NDH);
    const char* Vhp = (const char*)(g_Vh16 + (size_t)bh*NS*NDH);

    auto load_kv = [&](int t, int slot) {
        const uint32_t base = sb + A_KV + (uint32_t)slot*KV_STAGE;
        const size_t goff = (size_t)t * 64 * 128;   // 64 rows x 128B
        #pragma unroll
        for (int i = 0; i < 2; ++i) {
            const int e = tid + 256*i;
            const int row = e >> 3, seg = e & 7;
            const uint32_t sw = sw128((uint32_t)row*128u + seg*16u);
            const size_t off = goff + (size_t)row*128 + seg*16;
            cpa16(base + sw,         Khp + off);
            cpa16(base + 8192 + sw,  Vhp + off);
        }
        CP_COMMIT();
    };

    load_kv(0, 0);
    load_kv(1, 1);
    load_kv(2, 2);

    // load Q fp16 tile (64 rows x 128B)
    {
        const char* Qp = (const char*)(g_Qh16 + (size_t)(bh*NS + q0)*NDH);
        #pragma unroll
        for (int i = 0; i < 2; ++i) {
            const int e = tid + 256*i;
            const uint32_t off = (uint32_t)(e >> 3)*128u + (uint32_t)(e & 7)*16u;
            *reinterpret_cast<uint4*>(smem + A_Q + sw128(off)) =
                *reinterpret_cast<const uint4*>(Qp + off);
        }
    }
    __syncthreads();   // Q visible

    // preload Q fragments (reused across all 32 key tiles)
    const int qrow = qg*16 + lr + ((g & 1) ? 8 : 0);
    const int qcol = (g >= 2) ? 16 : 0;
    uint32_t qf[4][4];
    #pragma unroll
    for (int ks = 0; ks < 4; ++ks)
        ldsm_x4(qf[ks], sb + A_Q + sw128((uint32_t)qrow*128u + 32*ks + qcol));

    const int krow = lr + ((g >= 2) ? 8 : 0);
    const int kcol = (g & 1) ? 16 : 0;
    const int vrow = lr + ((g & 1) ? 8 : 0);
    const int vcol = (g >= 2) ? 16 : 0;

    float oacc[8][4];
    #pragma unroll
    for (int j = 0; j < 8; ++j)
        #pragma unroll
        for (int cI = 0; cI < 4; ++cI) oacc[j][cI] = 0.f;
    float lacc0 = 0.f, lacc1 = 0.f;

    const float MC = -1e9f * LOG2E;
    const float* mr0 = mask + ((size_t)b*NS + (q0 + qg*16 + r))*NS + 2*tq;
    const float* mr1 = mr0 + (size_t)8*NS;

    for (int t = 0; t < NS/64; ++t) {
        const int kt = t * 64;
        if (t < 30)      { asm volatile("cp.async.wait_group 2;" ::: "memory"); }
        else if (t == 30){ asm volatile("cp.async.wait_group 1;" ::: "memory"); }
        else             { asm volatile("cp.async.wait_group 0;" ::: "memory"); }
        __syncthreads();
        if (t + 3 < NS/64) load_kv(t + 3, (t + 3) & 3);

        const uint32_t stb = sb + A_KV + (uint32_t)(t & 3)*KV_STAGE;

        #pragma unroll
        for (int np = 0; np < 2; ++np) {
            const int nc = kh*2 + np;          // 16-key chunk index within 64
            // ---- S chunk (16 q-rows x 16 keys) = Qh @ Kh, 4 ILP chains ----
            float sA[4] = {0,0,0,0}, sB[4] = {0,0,0,0};
            float sC[4] = {0,0,0,0}, sD[4] = {0,0,0,0};
            {
                uint32_t k4[4];
                const uint32_t kbase = (uint32_t)(16*nc + krow)*128u + kcol;
                ldsm_x4(k4, stb + sw128(kbase));
                mma16816h(sA, qf[0], k4); mma16816h(sB, qf[0], k4+2);
                ldsm_x4(k4, stb + sw128(kbase + 32));
                mma16816h(sC, qf[1], k4); mma16816h(sD, qf[1], k4+2);
                ldsm_x4(k4, stb + sw128(kbase + 64));
                mma16816h(sA, qf[2], k4); mma16816h(sB, qf[2], k4+2);
                ldsm_x4(k4, stb + sw128(kbase + 96));
                mma16816h(sC, qf[3], k4); mma16816h(sD, qf[3], k4+2);
            }
            #pragma unroll
            for (int cI = 0; cI < 4; ++cI) { sA[cI] += sC[cI]; sB[cI] += sD[cI]; }

            // ---- softmax on this 16-key chunk (fp32 mask), pack P fragment ----
            uint32_t pa[4];
            #pragma unroll
            for (int jj = 0; jj < 2; ++jj) {
                const float* s4 = (jj == 0) ? sA : sB;
                const size_t ko = (size_t)(kt + nc*16 + 8*jj);
                const float2 f0 = *reinterpret_cast<const float2*>(mr0 + ko);
                const float2 f1 = *reinterpret_cast<const float2*>(mr1 + ko);
                const float p00 = ex2f(fmaf(f0.x, MC, s4[0]*LOG2E));
                const float p01 = ex2f(fmaf(f0.y, MC, s4[1]*LOG2E));
                const float p10 = ex2f(fmaf(f1.x, MC, s4[2]*LOG2E));
                const float p11 = ex2f(fmaf(f1.y, MC, s4[3]*LOG2E));
                lacc0 += p00 + p01;
                lacc1 += p10 + p11;
                pa[2*jj]     = pack_h2(p00, p01);
                pa[2*jj + 1] = pack_h2(p10, p11);
            }

            // ---- O += P @ V (16 keys of this chunk) ----
            #pragma unroll
            for (int nd = 0; nd < 4; ++nd) {
                const uint32_t vaddr = stb + 8192 +
                    sw128((uint32_t)(16*nc + vrow)*128u + 32*nd + vcol);
                uint32_t v4[4];
                ldsm_x4_t(v4, vaddr);
                mma16816h(oacc[2*nd],   pa, v4);
                mma16816h(oacc[2*nd+1], pa, v4+2);
            }
        }
        __syncthreads();
    }

    // ---- combine key-halves: warps kh=1 stash partials, kh=0 reduce+write ----
    float* buf = reinterpret_cast<float*>(smem + A_KV);
    __syncthreads();
    if (kh == 1) {
        float* p = buf + (size_t)(qg*32 + lane)*34;
        #pragma unroll
        for (int j = 0; j < 8; ++j)
            #pragma unroll
            for (int cI = 0; cI < 4; ++cI) p[j*4 + cI] = oacc[j][cI];
        p[32] = lacc0;
        p[33] = lacc1;
    }
    __syncthreads();
    if (kh == 0) {
        const float* p = buf + (size_t)(qg*32 + lane)*34;
        #pragma unroll
        for (int j = 0; j < 8; ++j)
            #pragma unroll
            for (int cI = 0; cI < 4; ++cI) oacc[j][cI] += p[j*4 + cI];
        lacc0 += p[32];
        lacc1 += p[33];

        lacc0 += __shfl_xor_sync(0xFFFFFFFF, lacc0, 1);
        lacc0 += __shfl_xor_sync(0xFFFFFFFF, lacc0, 2);
        lacc1 += __shfl_xor_sync(0xFFFFFFFF, lacc1, 1);
        lacc1 += __shfl_xor_sync(0xFFFFFFFF, lacc1, 2);
        const float inv0 = 1.f / lacc0;
        const float inv1 = 1.f / lacc1;

        const int row0 = b*NS + q0 + qg*16 + r;
        #pragma unroll
        for (int j = 0; j < 8; ++j) {
            const int col = h*NDH + 8*j + 2*tq;
            uint32_t hi, lo;
            split2h(oacc[j][0]*inv0, oacc[j][1]*inv0, hi, lo);
            *reinterpret_cast<uint32_t*>(&g_attnh16[(size_t)row0*512 + col]) = hi;
            *reinterpret_cast<uint32_t*>(&g_attnl16[(size_t)row0*512 + col]) = lo;
            split2h(oacc[j][2]*inv1, oacc[j][3]*inv1, hi, lo);
            *reinterpret_cast<uint32_t*>(&g_attnh16[(size_t)(row0+8)*512 + col]) = hi;
            *reinterpret_cast<uint32_t*>(&g_attnl16[(size_t)(row0+8)*512 + col]) = lo;
        }
    }
}

// ---------------------------------------------------------------------------
extern "C" void kernel_launch(void* const* d_in, const int* in_sizes, int n_in,
                              void* d_out, int out_size)
{
    const float* query = (const float*)d_in[0];
    const float* key   = (const float*)d_in[1];
    const float* value = (const float*)d_in[2];
    const float* mask  = (const float*)d_in[3];
    const float* wq    = (const float*)d_in[4];
    const float* bq    = (const float*)d_in[5];
    const float* wk    = (const float*)d_in[6];
    const float* bk    = (const float*)d_in[7];
    const float* wv    = (const float*)d_in[8];
    const float* bv    = (const float*)d_in[9];
    const float* wo    = (const float*)d_in[10];
    const float* bo    = (const float*)d_in[11];
    float* out = (float*)d_out;

    cudaFuncSetAttribute(gemm_mma_kernel<0>, cudaFuncAttributeMaxDynamicSharedMemorySize, 2*24576);
    cudaFuncSetAttribute(gemm_mma_kernel<1>, cudaFuncAttributeMaxDynamicSharedMemorySize, 2*32768);
    cudaFuncSetAttribute(attn_mma_kernel,    cudaFuncAttributeMaxDynamicSharedMemorySize, ATT_SMEM);

    dim3 gi(2048, 1, 3);
    conv_in_kernel<<<gi, 256>>>(query, key, value);
    dim3 gw(16, 16, 4);
    conv_w_kernel<<<gw, dim3(32, 8)>>>(wq, wk, wv, wo);

    dim3 gq(NDM/128, 4096/64, 3);           // (4, 64, 3)
    gemm_mma_kernel<0><<<gq, 256, 2*24576>>>(bq, bk, bv, nullptr);

    dim3 ga(NS/64, NB*NH);                  // (32, 16)
    attn_mma_kernel<<<ga, 256, ATT_SMEM>>>(mask);

    dim3 go(NDM/128, 4096/64);              // (4, 64)
    gemm_mma_kernel<1><<<go, 256, 2*32768>>>(bo, nullptr, nullptr, out);
}

// round 9
// speedup vs baseline: 1.0752x; 1.0752x over previous
#include <cuda_runtime.h>
#include <cuda_bf16.h>
#include <cuda_fp16.h>
#include <cstdint>

#define NB 2
#define NS 2048
#define NDM 512
#define NH 8
#define NDH 64
#define LOG2E 1.4426950408889634f

// ---------------------------------------------------------------------------
// Scratch (__device__ globals; no allocation allowed)
// ---------------------------------------------------------------------------
__device__ __half g_A16[3*4096*512];        // inputs (q,k,v), single fp16
__device__ __half g_Wt16[4*512*512];        // transposed weights [n][k], fp16
__device__ __half g_Qh16[NB*NH*NS*NDH];     // head-layout projections (fp16)
__device__ __half g_Kh16[NB*NH*NS*NDH];
__device__ __half g_Vh16[NB*NH*NS*NDH];
__device__ __half g_attnh16[4096*512];      // attention output hi (merged heads)
__device__ __half g_attnl16[4096*512];      // lo

// ---------------------------------------------------------------------------
// PTX helpers (baseline sm_80+ instructions only)
// ---------------------------------------------------------------------------
__device__ __forceinline__ uint32_t smem_u32(const void* p) {
    uint32_t a;
    asm("{ .reg .u64 t; cvta.to.shared.u64 t, %1; cvt.u32.u64 %0, t; }" : "=r"(a) : "l"(p));
    return a;
}
__device__ __forceinline__ void mma16816h(float* c, const uint32_t* a, const uint32_t* b) {
    asm volatile(
        "mma.sync.aligned.m16n8k16.row.col.f32.f16.f16.f32 "
        "{%0,%1,%2,%3}, {%4,%5,%6,%7}, {%8,%9}, {%0,%1,%2,%3};"
        : "+f"(c[0]), "+f"(c[1]), "+f"(c[2]), "+f"(c[3])
        : "r"(a[0]), "r"(a[1]), "r"(a[2]), "r"(a[3]), "r"(b[0]), "r"(b[1]));
}
__device__ __forceinline__ void ldsm_x4(uint32_t* r, uint32_t addr) {
    asm volatile("ldmatrix.sync.aligned.m8n8.x4.shared.b16 {%0,%1,%2,%3}, [%4];"
        : "=r"(r[0]), "=r"(r[1]), "=r"(r[2]), "=r"(r[3]) : "r"(addr));
}
__device__ __forceinline__ void ldsm_x4_t(uint32_t* r, uint32_t addr) {
    asm volatile("ldmatrix.sync.aligned.m8n8.x4.trans.shared.b16 {%0,%1,%2,%3}, [%4];"
        : "=r"(r[0]), "=r"(r[1]), "=r"(r[2]), "=r"(r[3]) : "r"(addr));
}
__device__ __forceinline__ void cpa16(uint32_t dst, const void* src) {
    asm volatile("cp.async.cg.shared.global [%0], [%1], 16;" :: "r"(dst), "l"(src));
}
#define CP_COMMIT() asm volatile("cp.async.commit_group;")
__device__ __forceinline__ uint32_t sw128(uint32_t off) {
    return off ^ ((off >> 3) & 0x70);
}
__device__ __forceinline__ float ex2f(float x) {
    float y; asm("ex2.approx.f32 %0, %1;" : "=f"(y) : "f"(x)); return y;
}
__device__ __forceinline__ uint32_t pack_h2(float a, float b) {
    __half2 t = __floats2half2_rn(a, b);
    return *reinterpret_cast<uint32_t*>(&t);
}
__device__ __forceinline__ void split2h(float v0, float v1, uint32_t& hi, uint32_t& lo) {
    __half h0 = __float2half_rn(v0);
    __half h1 = __float2half_rn(v1);
    __half l0 = __float2half_rn(v0 - __half2float(h0));
    __half l1 = __float2half_rn(v1 - __half2float(h1));
    __half2 hp = __halves2half2(h0, h1);
    __half2 lp = __halves2half2(l0, l1);
    hi = *reinterpret_cast<uint32_t*>(&hp);
    lo = *reinterpret_cast<uint32_t*>(&lp);
}

// ---------------------------------------------------------------------------
// Conversion kernels
// ---------------------------------------------------------------------------
__global__ void __launch_bounds__(256) conv_in_kernel(
    const float* __restrict__ q, const float* __restrict__ k, const float* __restrict__ v)
{
    const int z = blockIdx.z;
    const float* x = (z == 0) ? q : (z == 1) ? k : v;
    const size_t idx = ((size_t)blockIdx.x * 256 + threadIdx.x) * 4;
    float4 a = *reinterpret_cast<const float4*>(x + idx);
    const size_t o = (size_t)z * 4096 * 512 + idx;
    *reinterpret_cast<uint2*>(&g_A16[o]) =
        make_uint2(pack_h2(a.x, a.y), pack_h2(a.z, a.w));
}

__global__ void conv_w_kernel(
    const float* __restrict__ wq, const float* __restrict__ wk,
    const float* __restrict__ wv, const float* __restrict__ wo)
{
    const int z = blockIdx.z;
    const float* w = (z == 0) ? wq : (z == 1) ? wk : (z == 2) ? wv : wo;
    __shared__ float t[32][33];
    const int n0 = blockIdx.x * 32, k0 = blockIdx.y * 32;
    const int tx = threadIdx.x, ty = threadIdx.y;
    #pragma unroll
    for (int i = 0; i < 4; ++i)
        t[ty + 8*i][tx] = w[(size_t)(k0 + ty + 8*i) * 512 + n0 + tx];
    __syncthreads();
    #pragma unroll
    for (int i = 0; i < 4; ++i) {
        const int n = n0 + ty + 8*i, kk = k0 + tx;
        g_Wt16[(size_t)z * 262144 + (size_t)n * 512 + kk] = __float2half_rn(t[tx][ty + 8*i]);
    }
}

// ---------------------------------------------------------------------------
// fp16 HMMA GEMM, 64x128 tile, K-chunk 64, 8 warps (4m x 2n), 2-stage cp.async.
// MODE 0: qkv — A single fp16 (1 pass); writes fp16 head layout (Q scaled 1/8)
// MODE 1: out — A split hi+lo (2 passes, exact A); writes fp32 flat + bias
// ---------------------------------------------------------------------------
template<int MODE>
__global__ void __launch_bounds__(256, 2) gemm_mma_kernel(
    const float* __restrict__ b0, const float* __restrict__ b1,
    const float* __restrict__ b2, float* __restrict__ outp)
{
    constexpr uint32_t STAGE = (MODE == 0) ? 24576u : 32768u;  // A 8K (+Al 8K) + W 16K
    constexpr uint32_t WOFF  = (MODE == 0) ? 8192u  : 16384u;

    extern __shared__ char smem[];
    const uint32_t sb = smem_u32(smem);
    const int tid  = threadIdx.x;
    const int lane = tid & 31;
    const int warp = tid >> 5;
    const int wm   = warp & 3;
    const int wn   = warp >> 2;
    const int z    = (MODE == 0) ? blockIdx.z : 3;
    const int n0   = blockIdx.x * 128;
    const int m0   = blockIdx.y * 64;

    const char* Ah = (MODE == 0) ? (const char*)(g_A16 + (size_t)z*4096*512)
                                 : (const char*)g_attnh16;
    const char* Al = (const char*)g_attnl16;   // MODE 1 only
    const char* Wp = (const char*)(g_Wt16 + (size_t)z*262144);
    const float* bias = (MODE == 0) ? ((z == 0) ? b0 : (z == 1) ? b1 : b2) : b0;

    auto load_chunk = [&](int c, int st) {
        const uint32_t base = sb + (uint32_t)st * STAGE;
        #pragma unroll
        for (int i = 0; i < 2; ++i) {                 // A: 64 rows x 8 segs
            const int e = tid + 256*i;
            const int row = e >> 3, seg = e & 7;
            const uint32_t sw = sw128((uint32_t)row*128u + seg*16u);
            const size_t aoff = (size_t)(m0 + row)*1024 + (size_t)c*128 + seg*16;
            cpa16(base + sw, Ah + aoff);
            if (MODE == 1) cpa16(base + 8192 + sw, Al + aoff);
        }
        #pragma unroll
        for (int i = 0; i < 4; ++i) {                 // W: 128 rows x 8 segs
            const int e = tid + 256*i;
            const int row = e >> 3, seg = e & 7;
            const uint32_t sw = sw128((uint32_t)row*128u + seg*16u);
            const size_t woff = (size_t)(n0 + row)*1024 + (size_t)c*128 + seg*16;
            cpa16(base + WOFF + sw, Wp + woff);
        }
        CP_COMMIT();
    };

    float acc[8][4];
    #pragma unroll
    for (int bq = 0; bq < 8; ++bq)
        #pragma unroll
        for (int cI = 0; cI < 4; ++cI) acc[bq][cI] = 0.f;

    const int g  = lane >> 3, lr = lane & 7;
    const int arow = wm*16 + lr + ((g & 1) ? 8 : 0);
    const int acol = (g >= 2) ? 16 : 0;
    const int brow = lr + ((g >= 2) ? 8 : 0);
    const int bcol = (g & 1) ? 16 : 0;

    load_chunk(0, 0);
    for (int c = 0; c < 8; ++c) {
        if (c < 7) {
            load_chunk(c + 1, (c + 1) & 1);
            asm volatile("cp.async.wait_group 1;" ::: "memory");
        } else {
            asm volatile("cp.async.wait_group 0;" ::: "memory");
        }
        __syncthreads();
        const uint32_t stb = sb + (uint32_t)(c & 1) * STAGE;
        #pragma unroll
        for (int ks = 0; ks < 4; ++ks) {
            uint32_t ah0[4], al0[4];
            const uint32_t sw0 = sw128((uint32_t)arow*128u + 32*ks + acol);
            ldsm_x4(ah0, stb + sw0);
            if (MODE == 1) ldsm_x4(al0, stb + 8192 + sw0);
            #pragma unroll
            for (int np = 0; np < 4; ++np) {
                const uint32_t sw = sw128((uint32_t)(wn*64 + np*16 + brow)*128u + 32*ks + bcol);
                uint32_t w4[4];
                ldsm_x4(w4, stb + WOFF + sw);
                mma16816h(acc[2*np],   ah0, w4); mma16816h(acc[2*np+1], ah0, w4+2);
                if (MODE == 1) {
                    mma16816h(acc[2*np], al0, w4); mma16816h(acc[2*np+1], al0, w4+2);
                }
            }
        }
        __syncthreads();
    }

    // epilogue
    const int r  = lane >> 2;
    const int tq = lane & 3;
    const float sc = (MODE == 0 && z == 0) ? 0.125f : 1.f;
    __half* outh = (z == 0) ? g_Qh16 : (z == 1) ? g_Kh16 : g_Vh16;
    #pragma unroll
    for (int np = 0; np < 4; ++np) {
        #pragma unroll
        for (int sub = 0; sub < 2; ++sub) {
            const float* c4 = acc[2*np + sub];
            const int row0 = m0 + wm*16 + r;
            const int col  = n0 + wn*64 + np*16 + sub*8 + 2*tq;
            const float bv0 = bias[col], bv1 = bias[col + 1];
            if (MODE == 1) {
                *reinterpret_cast<float2*>(outp + (size_t)row0*512 + col) =
                    make_float2(c4[0] + bv0, c4[1] + bv1);
                *reinterpret_cast<float2*>(outp + (size_t)(row0+8)*512 + col) =
                    make_float2(c4[2] + bv0, c4[3] + bv1);
            } else {
                #pragma unroll
                for (int rr = 0; rr < 2; ++rr) {
                    const int row = row0 + rr*8;
                    const int bb = row >> 11, s = row & 2047;
                    const int hh = col >> 6,  d = col & 63;
                    const size_t o = (((size_t)bb*NH + hh)*NS + s)*NDH + d;
                    *reinterpret_cast<uint32_t*>(&outh[o]) =
                        pack_h2((c4[2*rr] + bv0)*sc, (c4[2*rr+1] + bv1)*sc);
                }
            }
        }
    }
}

// ---------------------------------------------------------------------------
// Flash attention (HMMA fp16), wide-M warps for fragment reuse.
// CTA = 128 queries, 4 warps, each warp owns 32 q-rows (two m16 fragments)
// against all 64 keys per tile: every K/V ldsm feeds 4 MMAs (2x reuse).
// 4-stage cp.async KV pipeline. fp32 mask inline. Writes split-fp16 output.
// ---------------------------------------------------------------------------
#define A_Q      0
#define A_KV     16384
#define KV_STAGE 16384          // Kh 8K | Vh 8K
#define ATT_SMEM (A_KV + 4*KV_STAGE)   // 81920

__global__ void __launch_bounds__(128) attn_mma_kernel(const float* __restrict__ mask)
{
    extern __shared__ char smem[];
    const uint32_t sb = smem_u32(smem);
    const int tid  = threadIdx.x;
    const int lane = tid & 31;
    const int qg   = tid >> 5;      // warp = q-group of 32 rows
    const int bh   = blockIdx.y;
    const int b    = bh >> 3;
    const int h    = bh & 7;
    const int q0   = blockIdx.x * 128;

    const int g  = lane >> 3, lr = lane & 7;
    const int r  = lane >> 2, tq = lane & 3;

    const char* Khp = (const char*)(g_Kh16 + (size_t)bh*NS*NDH);
    const char* Vhp = (const char*)(g_Vh16 + (size_t)bh*NS*NDH);

    auto load_kv = [&](int t, int slot) {
        const uint32_t base = sb + A_KV + (uint32_t)slot*KV_STAGE;
        const size_t goff = (size_t)t * 64 * 128;   // 64 rows x 128B
        #pragma unroll
        for (int i = 0; i < 4; ++i) {
            const int e = tid + 128*i;              // 512 (row,seg) pairs
            const int row = e >> 3, seg = e & 7;
            const uint32_t sw = sw128((uint32_t)row*128u + seg*16u);
            const size_t off = goff + (size_t)row*128 + seg*16;
            cpa16(base + sw,         Khp + off);
            cpa16(base + 8192 + sw,  Vhp + off);
        }
        CP_COMMIT();
    };

    load_kv(0, 0);
    load_kv(1, 1);
    load_kv(2, 2);

    // load Q fp16 tile (128 rows x 128B)
    {
        const char* Qp = (const char*)(g_Qh16 + (size_t)(bh*NS + q0)*NDH);
        #pragma unroll
        for (int i = 0; i < 8; ++i) {
            const int e = tid + 128*i;
            const uint32_t off = (uint32_t)(e >> 3)*128u + (uint32_t)(e & 7)*16u;
            *reinterpret_cast<uint4*>(smem + A_Q + sw128(off)) =
                *reinterpret_cast<const uint4*>(Qp + off);
        }
    }
    __syncthreads();   // Q visible

    // preload Q fragments: two m16 fragments (rows qg*32.. and +16), 4 k-steps
    const int qrow0 = qg*32 + lr + ((g & 1) ? 8 : 0);
    const int qcol  = (g >= 2) ? 16 : 0;
    uint32_t qf0[4][4], qf1[4][4];
    #pragma unroll
    for (int ks = 0; ks < 4; ++ks) {
        ldsm_x4(qf0[ks], sb + A_Q + sw128((uint32_t)qrow0*128u + 32*ks + qcol));
        ldsm_x4(qf1[ks], sb + A_Q + sw128((uint32_t)(qrow0 + 16)*128u + 32*ks + qcol));
    }

    const int krow = lr + ((g >= 2) ? 8 : 0);
    const int kcol = (g & 1) ? 16 : 0;
    const int vrow = lr + ((g & 1) ? 8 : 0);
    const int vcol = (g >= 2) ? 16 : 0;

    float oacc[2][8][4];
    #pragma unroll
    for (int m = 0; m < 2; ++m)
        #pragma unroll
        for (int j = 0; j < 8; ++j)
            #pragma unroll
            for (int cI = 0; cI < 4; ++cI) oacc[m][j][cI] = 0.f;
    float lacc[4] = {0.f, 0.f, 0.f, 0.f};   // rows r, r+8, r+16, r+24

    const float MC = -1e9f * LOG2E;
    const float* mr = mask + ((size_t)b*NS + (q0 + qg*32 + r))*NS + 2*tq;

    for (int t = 0; t < NS/64; ++t) {
        const int kt = t * 64;
        if (t < 30)      { asm volatile("cp.async.wait_group 2;" ::: "memory"); }
        else if (t == 30){ asm volatile("cp.async.wait_group 1;" ::: "memory"); }
        else             { asm volatile("cp.async.wait_group 0;" ::: "memory"); }
        __syncthreads();
        if (t + 3 < NS/64) load_kv(t + 3, (t + 3) & 3);

        const uint32_t stb = sb + A_KV + (uint32_t)(t & 3)*KV_STAGE;

        #pragma unroll
        for (int nc = 0; nc < 4; ++nc) {
            // ---- S chunk (32 q-rows x 16 keys) = Qh @ Kh ----
            float s0A[4] = {0,0,0,0}, s0B[4] = {0,0,0,0};
            float s1A[4] = {0,0,0,0}, s1B[4] = {0,0,0,0};
            #pragma unroll
            for (int ks = 0; ks < 4; ++ks) {
                uint32_t k4[4];
                ldsm_x4(k4, stb + sw128((uint32_t)(16*nc + krow)*128u + 32*ks + kcol));
                mma16816h(s0A, qf0[ks], k4); mma16816h(s0B, qf0[ks], k4+2);
                mma16816h(s1A, qf1[ks], k4); mma16816h(s1B, qf1[ks], k4+2);
            }

            // ---- softmax on this 16-key chunk (fp32 mask), pack P fragments ----
            uint32_t pa0[4], pa1[4];
            #pragma unroll
            for (int m = 0; m < 2; ++m) {
                const float* sA = (m == 0) ? s0A : s1A;
                const float* sB = (m == 0) ? s0B : s1B;
                uint32_t* pa = (m == 0) ? pa0 : pa1;
                const float* mra = mr + (size_t)(m*16)*NS;
                #pragma unroll
                for (int jj = 0; jj < 2; ++jj) {
                    const float* s4 = (jj == 0) ? sA : sB;
                    const size_t ko = (size_t)(kt + nc*16 + 8*jj);
                    const float2 f0 = *reinterpret_cast<const float2*>(mra + ko);
                    const float2 f1 = *reinterpret_cast<const float2*>(mra + (size_t)8*NS + ko);
                    const float p00 = ex2f(fmaf(f0.x, MC, s4[0]*LOG2E));
                    const float p01 = ex2f(fmaf(f0.y, MC, s4[1]*LOG2E));
                    const float p10 = ex2f(fmaf(f1.x, MC, s4[2]*LOG2E));
                    const float p11 = ex2f(fmaf(f1.y, MC, s4[3]*LOG2E));
                    lacc[m*2 + 0] += p00 + p01;
                    lacc[m*2 + 1] += p10 + p11;
                    pa[2*jj]     = pack_h2(p00, p01);
                    pa[2*jj + 1] = pack_h2(p10, p11);
                }
            }

            // ---- O += P @ V (16 keys of this chunk); V frags reused 2x ----
            #pragma unroll
            for (int nd = 0; nd < 4; ++nd) {
                uint32_t v4[4];
                ldsm_x4_t(v4, stb + 8192 + sw128((uint32_t)(16*nc + vrow)*128u + 32*nd + vcol));
                mma16816h(oacc[0][2*nd],   pa0, v4);
                mma16816h(oacc[0][2*nd+1], pa0, v4+2);
                mma16816h(oacc[1][2*nd],   pa1, v4);
                mma16816h(oacc[1][2*nd+1], pa1, v4+2);
            }
        }
        __syncthreads();
    }

    // row-sum reduce across the quad
    #pragma unroll
    for (int i = 0; i < 4; ++i) {
        lacc[i] += __shfl_xor_sync(0xFFFFFFFF, lacc[i], 1);
        lacc[i] += __shfl_xor_sync(0xFFFFFFFF, lacc[i], 2);
    }
    const float inv[4] = {1.f/lacc[0], 1.f/lacc[1], 1.f/lacc[2], 1.f/lacc[3]};

    // write split-fp16 merged-head output
    #pragma unroll
    for (int m = 0; m < 2; ++m) {
        const int row0 = b*NS + q0 + qg*32 + m*16 + r;
        #pragma unroll
        for (int j = 0; j < 8; ++j) {
            const int col = h*NDH + 8*j + 2*tq;
            uint32_t hi, lo;
            split2h(oacc[m][j][0]*inv[2*m], oacc[m][j][1]*inv[2*m], hi, lo);
            *reinterpret_cast<uint32_t*>(&g_attnh16[(size_t)row0*512 + col]) = hi;
            *reinterpret_cast<uint32_t*>(&g_attnl16[(size_t)row0*512 + col]) = lo;
            split2h(oacc[m][j][2]*inv[2*m+1], oacc[m][j][3]*inv[2*m+1], hi, lo);
            *reinterpret_cast<uint32_t*>(&g_attnh16[(size_t)(row0+8)*512 + col]) = hi;
            *reinterpret_cast<uint32_t*>(&g_attnl16[(size_t)(row0+8)*512 + col]) = lo;
        }
    }
}

// ---------------------------------------------------------------------------
extern "C" void kernel_launch(void* const* d_in, const int* in_sizes, int n_in,
                              void* d_out, int out_size)
{
    const float* query = (const float*)d_in[0];
    const float* key   = (const float*)d_in[1];
    const float* value = (const float*)d_in[2];
    const float* mask  = (const float*)d_in[3];
    const float* wq    = (const float*)d_in[4];
    const float* bq    = (const float*)d_in[5];
    const float* wk    = (const float*)d_in[6];
    const float* bk    = (const float*)d_in[7];
    const float* wv    = (const float*)d_in[8];
    const float* bv    = (const float*)d_in[9];
    const float* wo    = (const float*)d_in[10];
    const float* bo    = (const float*)d_in[11];
    float* out = (float*)d_out;

    cudaFuncSetAttribute(gemm_mma_kernel<0>, cudaFuncAttributeMaxDynamicSharedMemorySize, 2*24576);
    cudaFuncSetAttribute(gemm_mma_kernel<1>, cudaFuncAttributeMaxDynamicSharedMemorySize, 2*32768);
    cudaFuncSetAttribute(attn_mma_kernel,    cudaFuncAttributeMaxDynamicSharedMemorySize, ATT_SMEM);

    dim3 gi(2048, 1, 3);
    conv_in_kernel<<<gi, 256>>>(query, key, value);
    dim3 gw(16, 16, 4);
    conv_w_kernel<<<gw, dim3(32, 8)>>>(wq, wk, wv, wo);

    dim3 gq(NDM/128, 4096/64, 3);           // (4, 64, 3)
    gemm_mma_kernel<0><<<gq, 256, 2*24576>>>(bq, bk, bv, nullptr);

    dim3 ga(NS/128, NB*NH);                 // (16, 16)
    attn_mma_kernel<<<ga, 128, ATT_SMEM>>>(mask);

    dim3 go(NDM/128, 4096/64);              // (4, 64)
    gemm_mma_kernel<1><<<go, 256, 2*32768>>>(bo, nullptr, nullptr, out);
}